// round 8
// baseline (speedup 1.0000x reference)
#include <cuda_runtime.h>
#include <cstdint>
#include <cmath>

#define BB 512
#define NN 1000
#define CC 50
#define CCP 51              // pitch for transposed cluster tile (odd -> conflict-free)
#define EE 128
#define HH 8
#define DD 16
#define SPLIT 8
#define NPS (NN/SPLIT)
#define NEGV (-1e9f)
#define FUSE_ROWS (6*EE)    // 768 rows of weight prep work
#define NBQ 8               // batches per k_q block

// scratch (no cudaMalloc allowed)
__device__ float g_part[BB*SPLIT*2*EE];   // [b][split][{mask, mask|cmask}][e]
__device__ float g_Wqf [3*EE*EE];         // Wq @ mha_Wq   (384 x 128), [i][j]
__device__ float g_WkfT[EE*EE];           // (Wk @ mha_Wk)^T : [j][e]
__device__ float g_Wvf [EE*EE];           // Wv @ mha_Wv    : [e][j]
__device__ float g_WksT[EE*EE];           // Wks^T          : [f][e]
__device__ float g_kq  [BB*HH*EE];        // per-batch kq vectors

// ---------------------------------------------------------------------------
// Kernel 1: masked reduction (skip masked rows) + weight prep folded in.
// grid (BB, SPLIT+2), 128 threads.   (at HBM roofline — unchanged)
// ---------------------------------------------------------------------------
__global__ void __launch_bounds__(128) k_pre(
    const float* __restrict__ nodes,
    const int* __restrict__ mask, const int* __restrict__ cmask,
    const float* __restrict__ Wq, const float* __restrict__ Wk,
    const float* __restrict__ Wv, const float* __restrict__ Wks,
    const float* __restrict__ mWq, const float* __restrict__ mWk,
    const float* __restrict__ mWv)
{
    const int b = blockIdx.x, y = blockIdx.y, t = threadIdx.x;

    if (y >= SPLIT) {
        int fr = (y - SPLIT)*BB + b;
        if (fr >= FUSE_ROWS) return;
        if (fr < 3*EE) {
            float a = 0.f;
            #pragma unroll 8
            for (int e = 0; e < EE; e++) a += Wq[fr*EE + e] * mWq[e*EE + t];
            g_Wqf[fr*EE + t] = a;
        } else if (fr < 4*EE) {
            int e0 = fr - 3*EE;
            float a = 0.f;
            #pragma unroll 8
            for (int x = 0; x < EE; x++) a += Wk[e0*EE + x] * mWk[x*EE + t];
            g_WkfT[t*EE + e0] = a;           // store transposed
        } else if (fr < 5*EE) {
            int e0 = fr - 4*EE;
            float a = 0.f;
            #pragma unroll 8
            for (int x = 0; x < EE; x++) a += Wv[e0*EE + x] * mWv[x*EE + t];
            g_Wvf[e0*EE + t] = a;
        } else {
            int f = fr - 5*EE;
            g_WksT[f*EE + t] = Wks[t*EE + f];
        }
        return;
    }

    __shared__ uint8_t sM[NPS], sC[NPS];
    __shared__ float4  sP0[4][32];
    __shared__ float4  sP1[4][32];

    const int* m  = mask  + b*NN + y*NPS;
    const int* cm = cmask + b*NN + y*NPS;
    if (t < NPS) {
        sM[t] = (uint8_t)(m[t] != 0);
        sC[t] = (uint8_t)(cm[t] != 0);
    }
    __syncthreads();

    const int warp = t >> 5, lane = t & 31;
    const float4* base = (const float4*)(nodes + ((size_t)b*NN + (size_t)y*NPS)*EE);

    float4 a0 = make_float4(0.f,0.f,0.f,0.f);
    float4 a1 = make_float4(0.f,0.f,0.f,0.f);
    for (int r = warp; r < NPS; r += 4) {
        if (!sM[r]) {                        // warp-uniform: skip masked rows
            float4 v = __ldg(base + r*32 + lane);
            a0.x += v.x; a0.y += v.y; a0.z += v.z; a0.w += v.w;
            if (!sC[r]) { a1.x += v.x; a1.y += v.y; a1.z += v.z; a1.w += v.w; }
        }
    }
    sP0[warp][lane] = a0;
    sP1[warp][lane] = a1;
    __syncthreads();

    const float* p0 = (const float*)sP0;
    const float* p1 = (const float*)sP1;
    float s0 = p0[t] + p0[128 + t] + p0[256 + t] + p0[384 + t];
    float s1 = p1[t] + p1[128 + t] + p1[256 + t] + p1[384 + t];
    int idx = (b*SPLIT + y)*2*EE + t;
    g_part[idx]      = s0;
    g_part[idx + EE] = s1;
}

// ---------------------------------------------------------------------------
// Kernel 1.5: q + kq for 8 batches per block. Weight elements loaded ONCE
// per block serve 8 batches (register-tiled over batch).
// grid 64, 256 threads.
// ---------------------------------------------------------------------------
__global__ void __launch_bounds__(256) k_q(
    const float* __restrict__ cur, const float* __restrict__ depot)
{
    const int b0 = blockIdx.x * NBQ, t = threadIdx.x;
    const int j = t & 127, h2 = t >> 7;

    __shared__ float sCtx[NBQ][3*EE];
    __shared__ float sQp[2][NBQ*EE];
    __shared__ float sQ[NBQ][EE];

    // assemble context for 8 batches
    #pragma unroll
    for (int k = 0; k < 4; k++) {
        int idx = t + 256*k;                 // 1024 = 8*128
        int nb = idx >> 7, jj = idx & 127;
        int b = b0 + nb;
        float um = 0.f;
        #pragma unroll
        for (int s = 0; s < SPLIT; s++) um += g_part[(b*SPLIT + s)*2*EE + jj];
        sCtx[nb][jj]        = um * (1.f/NN);
        sCtx[nb][EE + jj]   = cur[b*EE + jj];
        sCtx[nb][2*EE + jj] = depot[b*EE + jj];
    }
    __syncthreads();

    // q[nb][j] = ctx[nb] . Wqf[:,j], split-K over halves, batch-tiled
    {
        const int i0 = h2*192;
        float acc[NBQ];
        #pragma unroll
        for (int nb = 0; nb < NBQ; nb++) acc[nb] = 0.f;
        for (int i = 0; i < 192; i++) {
            float w = g_Wqf[(i0 + i)*EE + j];
            #pragma unroll
            for (int nb = 0; nb < NBQ; nb++) acc[nb] += sCtx[nb][i0 + i] * w;
        }
        #pragma unroll
        for (int nb = 0; nb < NBQ; nb++) sQp[h2][nb*EE + j] = acc[nb];
    }
    __syncthreads();
    #pragma unroll
    for (int k = 0; k < 4; k++) {
        int idx = t + 256*k;
        sQ[idx >> 7][idx & 127] = sQp[0][idx] + sQp[1][idx];
    }
    __syncthreads();

    // kq[nb][h][e] = sum_d q[nb][h*16+d] * WkfT[h*16+d][e], batch-tiled
    {
        const int e = j;
        #pragma unroll
        for (int hh = 0; hh < 4; hh++) {
            int h = h2*4 + hh;
            float acc[NBQ];
            #pragma unroll
            for (int nb = 0; nb < NBQ; nb++) acc[nb] = 0.f;
            #pragma unroll
            for (int d = 0; d < DD; d++) {
                float w = g_WkfT[(h*DD + d)*EE + e];
                #pragma unroll
                for (int nb = 0; nb < NBQ; nb++)
                    acc[nb] += sQ[nb][h*DD + d] * w;
            }
            #pragma unroll
            for (int nb = 0; nb < NBQ; nb++)
                g_kq[(size_t)(b0 + nb)*HH*EE + h*EE + e] = acc[nb];
        }
    }
}

// ---------------------------------------------------------------------------
// Kernel 2: attention + logits + outputs. 256 threads/block, one batch/block.
// ---------------------------------------------------------------------------
__global__ void __launch_bounds__(256) k_main(
    const float* __restrict__ depot, const float* __restrict__ CE,
    const float* __restrict__ cur,   const float* __restrict__ augc,
    const float* __restrict__ gein,  const float* __restrict__ Wo,
    const int* __restrict__ isnew, const int* __restrict__ vcm_g,
    const int* __restrict__ guid_in, float* __restrict__ out)
{
    const int b = blockIdx.x, t = threadIdx.x;
    const int t2 = t & 127, half = t >> 7;
    const int warp = t >> 5, lane = t & 31;

    __shared__ float sCET[EE*CCP];     // transposed cluster embeddings
    __shared__ float sCur[EE], sDep[EE];
    __shared__ float sUC[EE];
    __shared__ float sP2[2][EE];       // split-K partials (reused per stage)
    __shared__ float sKQ[HH*EE];
    __shared__ float sSc[HH*CC];
    __shared__ float sAt[HH*CC];
    __shared__ float sAce[HH*EE];
    __shared__ float sGl[EE];
    __shared__ float sOut[EE];
    __shared__ float sW2[EE];
    __shared__ float sLgP[4][CC];
    __shared__ float sLg[CC];
    __shared__ int   sVcm[CC];
    __shared__ float sMax, sLse;
    __shared__ int   sArg;

    // ---- load cluster embeddings transposed; kq into smem ----
    {
        const float* src = CE + (size_t)b*CC*EE;
        #pragma unroll
        for (int cc = 0; cc < 25; cc++) {
            int c = half*25 + cc;
            sCET[t2*CCP + c] = src[c*EE + t2];
        }
        #pragma unroll
        for (int k = 0; k < 4; k++)
            sKQ[t + 256*k] = g_kq[(size_t)b*HH*EE + t + 256*k];
    }

    // ---- uc combine (half 0), cur/depot (half 1) ----
    if (half == 0) {
        float a = 0.f;
        #pragma unroll
        for (int s = 0; s < SPLIT; s++)
            a += g_part[(b*SPLIT + s)*2*EE + EE + t2];
        sUC[t2] = a * (1.f/NN);
    } else {
        sCur[t2] = cur[b*EE + t2];
        sDep[t2] = depot[b*EE + t2];
    }
    if (t < CC) sVcm[t] = (vcm_g[b*CC + t] != 0);
    __syncthreads();

    if (t == 0) {                      // vcm[0] = !all(vcm[1:])
        int all = 1;
        for (int c = 1; c < CC; c++) all &= (sVcm[c] != 0);
        sVcm[0] = !all;
    }
    __syncthreads();

    // ---- scores: warp = head; lanes own c=lane, c=lane+32; kq broadcast ----
    {
        const int h = warp;
        const int c0 = lane;
        const int c1 = (lane + 32 < CC) ? lane + 32 : CC - 1;  // clamped (safe read)
        float a00=0.f,a01=0.f,a10=0.f,a11=0.f;
        #pragma unroll 4
        for (int e = 0; e < EE; e += 2) {
            float k0 = sKQ[h*EE + e];       // broadcast
            float k1 = sKQ[h*EE + e + 1];
            a00 += sCET[(e  )*CCP + c0] * k0;
            a01 += sCET[(e+1)*CCP + c0] * k1;
            a10 += sCET[(e  )*CCP + c1] * k0;
            a11 += sCET[(e+1)*CCP + c1] * k1;
        }
        float s0 = (a00 + a01) * 0.25f;
        float s1 = (a10 + a11) * 0.25f;
        if (sVcm[c0]) s0 = NEGV;
        sSc[h*CC + c0] = s0;
        if (lane + 32 < CC) {
            if (sVcm[c1]) s1 = NEGV;
            sSc[h*CC + c1] = s1;
        }
    }
    __syncthreads();

    // ---- softmax: warp h owns head h ----
    {
        int h = warp;
        float v0 = sSc[h*CC + lane];
        float v1 = (lane < CC-32) ? sSc[h*CC + lane + 32] : -3e38f;
        float mx = fmaxf(v0, v1);
        #pragma unroll
        for (int o = 16; o > 0; o >>= 1)
            mx = fmaxf(mx, __shfl_xor_sync(0xffffffffu, mx, o));
        float e0 = expf(v0 - mx);
        float e1 = (lane < CC-32) ? expf(v1 - mx) : 0.f;
        float sm = e0 + e1;
        #pragma unroll
        for (int o = 16; o > 0; o >>= 1)
            sm += __shfl_xor_sync(0xffffffffu, sm, o);
        float inv = 1.f / sm;
        sAt[h*CC + lane] = e0 * inv;
        if (lane < CC-32) sAt[h*CC + lane + 32] = e1 * inv;
    }
    __syncthreads();

    // ---- a_ce: warp = head; thread owns 4 strided e; attn broadcast ----
    {
        const int h = warp;
        float a0=0.f,a1=0.f,a2=0.f,a3=0.f;
        #pragma unroll 2
        for (int c = 0; c < CC; c++) {
            float at = sAt[h*CC + c];       // broadcast
            a0 += at * sCET[(lane      )*CCP + c];
            a1 += at * sCET[(lane +  32)*CCP + c];
            a2 += at * sCET[(lane +  64)*CCP + c];
            a3 += at * sCET[(lane +  96)*CCP + c];
        }
        sAce[h*EE + lane      ] = a0;
        sAce[h*EE + lane +  32] = a1;
        sAce[h*EE + lane +  64] = a2;
        sAce[h*EE + lane +  96] = a3;
    }
    __syncthreads();

    // ---- glimpse[j=t2]: 128-MAC split-K over halves (h = j/16) ----
    {
        int h = t2 / DD;
        const int e0 = half*64;
        float a0=0.f,a1=0.f,a2=0.f,a3=0.f;
        #pragma unroll 4
        for (int e = 0; e < 64; e += 4) {
            a0 += sAce[h*EE + e0+e  ] * g_Wvf[(e0+e  )*EE + t2];
            a1 += sAce[h*EE + e0+e+1] * g_Wvf[(e0+e+1)*EE + t2];
            a2 += sAce[h*EE + e0+e+2] * g_Wvf[(e0+e+2)*EE + t2];
            a3 += sAce[h*EE + e0+e+3] * g_Wvf[(e0+e+3)*EE + t2];
        }
        sP2[half][t2] = (a0+a1)+(a2+a3);
    }
    __syncthreads();
    if (half == 0) sGl[t2] = sP2[0][t2] + sP2[1][t2];
    __syncthreads();

    // ---- out = glimpse @ Wo: split-K over halves ----
    {
        const int j0 = half*64;
        float a0=0.f,a1=0.f,a2=0.f,a3=0.f;
        #pragma unroll 4
        for (int j = 0; j < 64; j += 4) {
            a0 += sGl[j0+j  ] * Wo[(j0+j  )*EE + t2];
            a1 += sGl[j0+j+1] * Wo[(j0+j+1)*EE + t2];
            a2 += sGl[j0+j+2] * Wo[(j0+j+2)*EE + t2];
            a3 += sGl[j0+j+3] * Wo[(j0+j+3)*EE + t2];
        }
        sP2[half][t2] = (a0+a1)+(a2+a3);
    }
    __syncthreads();
    if (half == 0) sOut[t2] = sP2[0][t2] + sP2[1][t2];
    __syncthreads();

    // ---- w2[e=t2]: split-K over halves ----
    {
        const int f0 = half*64;
        float a0=0.f,a1=0.f,a2=0.f,a3=0.f;
        #pragma unroll 4
        for (int f = 0; f < 64; f += 4) {
            a0 += g_WksT[(f0+f  )*EE + t2] * sOut[f0+f  ];
            a1 += g_WksT[(f0+f+1)*EE + t2] * sOut[f0+f+1];
            a2 += g_WksT[(f0+f+2)*EE + t2] * sOut[f0+f+2];
            a3 += g_WksT[(f0+f+3)*EE + t2] * sOut[f0+f+3];
        }
        sP2[half][t2] = (a0+a1)+(a2+a3);
    }
    __syncthreads();
    if (half == 0) sW2[t2] = sP2[0][t2] + sP2[1][t2];
    __syncthreads();

    // ---- logit[c]: 50 outputs, split over 4 quarters of e ----
    {
        int c = t & 63, q4 = t >> 6;
        if (c < CC) {
            const int e0 = q4*32;
            float a0=0.f,a1=0.f;
            #pragma unroll 4
            for (int e = 0; e < 32; e += 2) {
                a0 += sCET[(e0+e  )*CCP + c] * sW2[e0+e  ];
                a1 += sCET[(e0+e+1)*CCP + c] * sW2[e0+e+1];
            }
            sLgP[q4][c] = a0 + a1;
        }
    }
    __syncthreads();
    if (t < CC) {
        float a = (sLgP[0][t] + sLgP[1][t]) + (sLgP[2][t] + sLgP[3][t]);
        a *= 0.08838834764831845f;     // 1/sqrt(128)
        a = tanhf(a) * 10.f;
        if (sVcm[t]) a = NEGV;
        sLg[t] = a;
    }
    __syncthreads();

    // ---- argmax (first-index ties) + logsumexp, warp 0 via shfl ----
    if (warp == 0) {
        float v0 = sLg[lane];
        float v1 = (lane < CC-32) ? sLg[lane + 32] : -3e38f;
        float v = v0; int ix = lane;
        if (v1 > v) { v = v1; ix = lane + 32; }
        #pragma unroll
        for (int o = 16; o > 0; o >>= 1) {
            float ov = __shfl_xor_sync(0xffffffffu, v, o);
            int   oi = __shfl_xor_sync(0xffffffffu, ix, o);
            if (ov > v || (ov == v && oi < ix)) { v = ov; ix = oi; }
        }
        float mx = v;
        float sm = expf(v0 - mx) + ((lane < CC-32) ? expf(v1 - mx) : 0.f);
        #pragma unroll
        for (int o = 16; o > 0; o >>= 1)
            sm += __shfl_xor_sync(0xffffffffu, sm, o);
        if (lane == 0) { sMax = mx; sLse = logf(sm); sArg = ix; }
    }
    __syncthreads();

    const int  guid = sArg;
    const bool isn  = isnew[b] != 0;
    const float ge  = sCET[t2*CCP + guid];

    const size_t OFF1 = (size_t)BB*4*EE;            // guid_embed_out
    const size_t OFF2 = OFF1 + (size_t)BB*EE;       // guid_out
    const size_t OFF3 = OFF2 + BB;                  // clu_prob

    float* ao = out + (size_t)b*4*EE;
    const float* ac = augc + (size_t)b*4*EE;
    if (half == 0) {
        ao[t2]        = isn ? sUC[t2]  : ac[t2];
        ao[2*EE + t2] = isn ? ge       : ac[2*EE + t2];
        out[OFF1 + (size_t)b*EE + t2] = isn ? ge : gein[b*EE + t2];
    } else {
        ao[EE + t2]   = isn ? sCur[t2] : ac[EE + t2];
        ao[3*EE + t2] = isn ? sDep[t2] : ac[3*EE + t2];
    }
    if (t == 0) out[OFF2 + b] = (float)(isn ? guid : guid_in[b]);
    if (t < CC) out[OFF3 + (size_t)b*CC + t] = isn ? (sLg[t] - sMax - sLse) : 0.f;
}

// ---------------------------------------------------------------------------
extern "C" void kernel_launch(void* const* d_in, const int* in_sizes, int n_in,
                              void* d_out, int out_size) {
    const float* depot = (const float*)d_in[0];
    const float* CE    = (const float*)d_in[1];
    const float* cur   = (const float*)d_in[2];
    const float* nodes = (const float*)d_in[3];
    const float* augc  = (const float*)d_in[4];
    const float* gein  = (const float*)d_in[5];
    const float* Wq    = (const float*)d_in[6];
    const float* Wk    = (const float*)d_in[7];
    const float* Wv    = (const float*)d_in[8];
    const float* Wks   = (const float*)d_in[9];
    const float* mWq   = (const float*)d_in[10];
    const float* mWk   = (const float*)d_in[11];
    const float* mWv   = (const float*)d_in[12];
    const float* Wo    = (const float*)d_in[13];
    const int* isnew   = (const int*)d_in[14];   // bool -> int32
    const int* mask    = (const int*)d_in[15];   // bool -> int32
    const int* cmask   = (const int*)d_in[16];   // bool -> int32
    const int* vcm     = (const int*)d_in[17];   // bool -> int32
    const int* guid    = (const int*)d_in[18];
    // d_in[19] = step (unused)

    dim3 gr(BB, SPLIT + 2);   // 8 reduce planes + 2 prep planes
    k_pre<<<gr, 128>>>(nodes, mask, cmask, Wq, Wk, Wv, Wks, mWq, mWk, mWv);
    k_q<<<BB/NBQ, 256>>>(cur, depot);
    k_main<<<BB, 256>>>(depot, CE, cur, augc, gein, Wo, isnew, vcm, guid,
                        (float*)d_out);
}